// round 16
// baseline (speedup 1.0000x reference)
#include <cuda_runtime.h>
#include <cuda_fp16.h>
#include <cstdint>

// SDDMM: out[i] = mask_vals[i] + dot(mat1[rows[i], :], mat2[:, cols[i]])
// Inputs: mask_vals f32[1e6], rows i32[1e6], cols i32[1e6],
//         mat1 f32[8192,128], mat2 f32[128,8192]   Output: f32[1e6]
//
// Single persistent kernel: Phase A stages mat1/mat2 as fp16 and packs
// {key,mask}; device-wide barrier; Phase B = R15's proven SDDMM loop.
// Grid 1184 = 148 SMs x 8 blocks, __launch_bounds__(256,8) guarantees
// co-residency of every block -> the spin barrier cannot deadlock.

#define NNZ  1000000
#define MDIM 8192
#define NDIM 8192
#define KDIM 128

#define GRID_BLOCKS 1184               // 148 * 8, one wave exactly

__device__ __half        g_m1h[(size_t)MDIM * KDIM];   // mat1 fp16 [M, K]
__device__ __half        g_m2Th[(size_t)NDIM * KDIM];  // mat2^T fp16 [N, K]
__device__ uint2         g_rcm[NNZ];                   // { (row<<13)|col, mask }
__device__ unsigned int  g_bar;                        // monotonic barrier ctr

// ---------------------------------------------------------------------------
// Dot of 8 half pairs: HMUL2/HFMA2 depth-2 chains, one fp32 conversion.
// ---------------------------------------------------------------------------
__device__ __forceinline__ float dot8h(float4 av, float4 bv) {
    const __half2* ah = reinterpret_cast<const __half2*>(&av);
    const __half2* bh = reinterpret_cast<const __half2*>(&bv);
    __half2 p0 = __hmul2(ah[0], bh[0]);
    p0 = __hfma2(ah[1], bh[1], p0);
    __half2 p1 = __hmul2(ah[2], bh[2]);
    p1 = __hfma2(ah[3], bh[3], p1);
    const float2 f0 = __half22float2(p0);
    const float2 f1 = __half22float2(p1);
    return (f0.x + f0.y) + (f1.x + f1.y);
}

__global__ void __launch_bounds__(256, 8)
fused_k(const float* __restrict__ mat1, const float* __restrict__ mat2,
        const int* __restrict__ rows, const int* __restrict__ cols,
        const float* __restrict__ mask_vals, float* __restrict__ out) {
    const int tid  = threadIdx.x;
    const int bid  = blockIdx.x;
    const int gtid = bid * 256 + tid;

    // ================= Phase A: staging =================
    // A1: transpose-convert mat2 [K,N] -> g_m2Th [N,K] fp16 (1024 tiles)
    __shared__ float tile[32][33];
    if (bid < 1024) {
        const int tx = tid & 31;
        const int ty = tid >> 5;
        const int n0 = (bid & 255) * 32;
        const int k0 = (bid >> 8) * 32;
        #pragma unroll
        for (int r = ty; r < 32; r += 8)
            tile[r][tx] = mat2[(size_t)(k0 + r) * NDIM + n0 + tx];
        __syncthreads();
        const int l16 = tid & 15;
        const int h   = tid >> 4;
        #pragma unroll
        for (int rr = h; rr < 32; rr += 16) {
            const __half2 hh = __floats2half2_rn(tile[2 * l16][rr],
                                                 tile[2 * l16 + 1][rr]);
            reinterpret_cast<unsigned int*>(
                g_m2Th + (size_t)(n0 + rr) * KDIM + k0)[l16] =
                *reinterpret_cast<const unsigned int*>(&hh);
        }
    }

    // A2: convert mat1 -> fp16. 262144 float4 total, one per thread.
    if (gtid < (MDIM * KDIM / 4)) {
        const float4 v = reinterpret_cast<const float4*>(mat1)[gtid];
        __half2 h0 = __floats2half2_rn(v.x, v.y);
        __half2 h1 = __floats2half2_rn(v.z, v.w);
        uint2 pack;
        pack.x = *reinterpret_cast<unsigned int*>(&h0);
        pack.y = *reinterpret_cast<unsigned int*>(&h1);
        reinterpret_cast<uint2*>(g_m1h)[gtid] = pack;
    }

    // A3: pack {key, mask} -> g_rcm, 4 nnz per thread (250000 threads).
    if (gtid < (NNZ / 4)) {
        const int base = gtid * 4;
        const int4   r = *reinterpret_cast<const int4*>(rows + base);
        const int4   c = *reinterpret_cast<const int4*>(cols + base);
        const float4 m = *reinterpret_cast<const float4*>(mask_vals + base);
        uint4 q0, q1;
        q0.x = ((unsigned)r.x << 13) | (unsigned)c.x;
        q0.y = __float_as_uint(m.x);
        q0.z = ((unsigned)r.y << 13) | (unsigned)c.y;
        q0.w = __float_as_uint(m.y);
        q1.x = ((unsigned)r.z << 13) | (unsigned)c.z;
        q1.y = __float_as_uint(m.z);
        q1.z = ((unsigned)r.w << 13) | (unsigned)c.w;
        q1.w = __float_as_uint(m.w);
        reinterpret_cast<uint4*>(g_rcm + base)[0] = q0;
        reinterpret_cast<uint4*>(g_rcm + base)[1] = q1;
    }

    // ================= Device-wide barrier =================
    // All 1184 blocks are resident (launch_bounds(256,8) -> 8 blocks/SM).
    // Monotonic counter: works across graph replays without reset.
    __syncthreads();
    if (tid == 0) {
        __threadfence();                               // publish phase-A writes
        const unsigned old    = atomicAdd(&g_bar, 1u);
        const unsigned target = (old / GRID_BLOCKS + 1u) * GRID_BLOCKS;
        while (*(volatile unsigned*)&g_bar < target) { }
        __threadfence();                               // acquire
    }
    __syncthreads();

    // ================= Phase B: SDDMM (R15 loop, verbatim) =================
    const int lane   = tid & 31;
    const int sub    = lane & 7;
    const int grp    = lane >> 3;
    const int gwarp  = gtid >> 5;
    const int nwarps = (GRID_BLOCKS * 256) >> 5;
    const int stride = nwarps * 4;

    int base = gwarp * 4;
    if (base >= NNZ) return;

    uint2 rm = g_rcm[base + grp];

    while (base < NNZ) {
        const int r = (int)(rm.x >> 13);
        const int c = (int)(rm.x & 8191u);

        const float4* __restrict__ a4 =
            reinterpret_cast<const float4*>(g_m1h + (size_t)r * KDIM);
        const float4* __restrict__ b4 =
            reinterpret_cast<const float4*>(g_m2Th + (size_t)c * KDIM);

        const float4 aL = a4[sub];
        const float4 bL = b4[sub];
        const float4 aH = a4[sub + 8];
        const float4 bH = b4[sub + 8];

        const int nbase = base + stride;
        uint2 rm_next = rm;
        if (nbase < NNZ) rm_next = g_rcm[nbase + grp];

        float s = dot8h(aL, bL) + dot8h(aH, bH);

        s += __shfl_xor_sync(0xFFFFFFFFu, s, 4);
        s += __shfl_xor_sync(0xFFFFFFFFu, s, 2);
        s += __shfl_xor_sync(0xFFFFFFFFu, s, 1);

        if (sub == 0)
            out[base + grp] = __uint_as_float(rm.y) + s;

        base = nbase;
        rm   = rm_next;
    }
}

extern "C" void kernel_launch(void* const* d_in, const int* in_sizes, int n_in,
                              void* d_out, int out_size) {
    const float* mask_vals = (const float*)d_in[0];
    const int*   rows      = (const int*)d_in[1];
    const int*   cols      = (const int*)d_in[2];
    const float* mat1      = (const float*)d_in[3];
    const float* mat2      = (const float*)d_in[4];
    float*       out       = (float*)d_out;

    fused_k<<<GRID_BLOCKS, 256>>>(mat1, mat2, rows, cols, mask_vals, out);
}

// round 17
// speedup vs baseline: 1.1732x; 1.1732x over previous
#include <cuda_runtime.h>
#include <cuda_fp16.h>
#include <cstdint>

// SDDMM: out[i] = mask_vals[i] + dot(mat1[rows[i], :], mat2[:, cols[i]])
// Inputs: mask_vals f32[1e6], rows i32[1e6], cols i32[1e6],
//         mat1 f32[8192,128], mat2 f32[128,8192]   Output: f32[1e6]
//
// R15 structure (fp16-staged gathers, HFMA2 depth-2 dot, fused {key,mask},
// 1-deep idx prefetch) + PDL: sddmm launches programmatically while prep
// drains; it syncs on grid dependencies only before touching staged data.

#define NNZ  1000000
#define MDIM 8192
#define NDIM 8192
#define KDIM 128

__device__ __half g_m1h[(size_t)MDIM * KDIM];   // mat1 fp16 [M, K]
__device__ __half g_m2Th[(size_t)NDIM * KDIM];  // mat2^T fp16 [N, K]
__device__ uint2  g_rcm[NNZ];                   // { (row<<13)|col, mask bits }

// ---------------------------------------------------------------------------
// Fused prep (one launch):
//   [0, 1024):     transpose-convert mat2 -> g_m2Th (half2 stores)
//   [1024, 1280):  convert mat1 -> fp16 (256*256*4 = 262144 == MDIM*KDIM/4)
//   [1280, 2257):  pack {key, mask} -> g_rcm (977*256*4 = 1000448 >= NNZ)
// ---------------------------------------------------------------------------
#define T2_BLOCKS  1024
#define C1_BLOCKS  256
#define RC_BLOCKS  977

__global__ void __launch_bounds__(256)
prep_k(const float* __restrict__ mat1, const float* __restrict__ mat2,
       const int* __restrict__ rows, const int* __restrict__ cols,
       const float* __restrict__ mask_vals) {
    if (blockIdx.x < T2_BLOCKS) {
        // ---- transpose-convert mat2: tile [k:32][n:32] ----
        __shared__ float tile[32][33];
        const int tx = threadIdx.x & 31;
        const int ty = threadIdx.x >> 5;
        const int n0 = (blockIdx.x & 255) * 32;
        const int k0 = (blockIdx.x >> 8) * 32;
        #pragma unroll
        for (int r = ty; r < 32; r += 8)
            tile[r][tx] = mat2[(size_t)(k0 + r) * NDIM + n0 + tx];
        __syncthreads();
        const int l16 = threadIdx.x & 15;
        const int h   = threadIdx.x >> 4;
        #pragma unroll
        for (int rr = h; rr < 32; rr += 16) {
            const __half2 hh = __floats2half2_rn(tile[2 * l16][rr],
                                                 tile[2 * l16 + 1][rr]);
            reinterpret_cast<unsigned int*>(
                g_m2Th + (size_t)(n0 + rr) * KDIM + k0)[l16] =
                *reinterpret_cast<const unsigned int*>(&hh);
        }
    } else if (blockIdx.x < T2_BLOCKS + C1_BLOCKS) {
        // ---- linear convert mat1 (MLP=4) ----
        const int b  = blockIdx.x - T2_BLOCKS;
        const int t0 = (b * 256 + threadIdx.x) * 4;
        float4 v[4];
        #pragma unroll
        for (int j = 0; j < 4; j++)
            v[j] = reinterpret_cast<const float4*>(mat1)[t0 + j];
        #pragma unroll
        for (int j = 0; j < 4; j++) {
            __half2 h0 = __floats2half2_rn(v[j].x, v[j].y);
            __half2 h1 = __floats2half2_rn(v[j].z, v[j].w);
            uint2 pack;
            pack.x = *reinterpret_cast<unsigned int*>(&h0);
            pack.y = *reinterpret_cast<unsigned int*>(&h1);
            reinterpret_cast<uint2*>(g_m1h)[t0 + j] = pack;
        }
    } else {
        // ---- pack {key, mask} -> g_rcm (MLP=3) ----
        const int b    = blockIdx.x - T2_BLOCKS - C1_BLOCKS;
        const int base = (b * 256 + threadIdx.x) * 4;
        if (base < NNZ) {
            const int4   r = *reinterpret_cast<const int4*>(rows + base);
            const int4   c = *reinterpret_cast<const int4*>(cols + base);
            const float4 m = *reinterpret_cast<const float4*>(mask_vals + base);
            uint4 q0, q1;
            q0.x = ((unsigned)r.x << 13) | (unsigned)c.x;
            q0.y = __float_as_uint(m.x);
            q0.z = ((unsigned)r.y << 13) | (unsigned)c.y;
            q0.w = __float_as_uint(m.y);
            q1.x = ((unsigned)r.z << 13) | (unsigned)c.z;
            q1.y = __float_as_uint(m.z);
            q1.z = ((unsigned)r.w << 13) | (unsigned)c.w;
            q1.w = __float_as_uint(m.w);
            reinterpret_cast<uint4*>(g_rcm + base)[0] = q0;
            reinterpret_cast<uint4*>(g_rcm + base)[1] = q1;
        }
    }
    // Allow the dependent sddmm launch to begin its prologue.
    cudaTriggerProgrammaticLaunchCompletion();
}

// ---------------------------------------------------------------------------
// Dot of 8 half pairs: HMUL2/HFMA2 depth-2 chains, one fp32 conversion.
// ---------------------------------------------------------------------------
__device__ __forceinline__ float dot8h(float4 av, float4 bv) {
    const __half2* ah = reinterpret_cast<const __half2*>(&av);
    const __half2* bh = reinterpret_cast<const __half2*>(&bv);
    __half2 p0 = __hmul2(ah[0], bh[0]);
    p0 = __hfma2(ah[1], bh[1], p0);
    __half2 p1 = __hmul2(ah[2], bh[2]);
    p1 = __hfma2(ah[3], bh[3], p1);
    const float2 f0 = __half22float2(p0);
    const float2 f1 = __half22float2(p1);
    return (f0.x + f0.y) + (f1.x + f1.y);
}

// ---------------------------------------------------------------------------
// Grid-stride SDDMM (R15 loop): 8 lanes/nnz, 4 nnz/warp-iter, {key,mask}
// software-pipelined one iteration ahead. PDL: prologue runs during prep's
// tail; grid-dependency sync gates the first staged-data access.
// ---------------------------------------------------------------------------
__global__ void __launch_bounds__(256)
sddmm_k(float* __restrict__ out) {
    // ---- index-only prologue (independent of prep results) ----
    const int lane   = threadIdx.x & 31;
    const int sub    = lane & 7;
    const int grp    = lane >> 3;
    const int gwarp  = (blockIdx.x * blockDim.x + threadIdx.x) >> 5;
    const int nwarps = (gridDim.x * blockDim.x) >> 5;
    const int stride = nwarps * 4;

    int base = gwarp * 4;

    // ---- wait for prep's writes to be visible ----
    cudaGridDependencySynchronize();

    if (base >= NNZ) return;

    uint2 rm = g_rcm[base + grp];              // first {key, mask}

    while (base < NNZ) {
        const int r = (int)(rm.x >> 13);
        const int c = (int)(rm.x & 8191u);

        const float4* __restrict__ a4 =
            reinterpret_cast<const float4*>(g_m1h + (size_t)r * KDIM);
        const float4* __restrict__ b4 =
            reinterpret_cast<const float4*>(g_m2Th + (size_t)c * KDIM);

        // 4 independent data LDG.128
        const float4 aL = a4[sub];
        const float4 bL = b4[sub];
        const float4 aH = a4[sub + 8];
        const float4 bH = b4[sub + 8];

        // Prefetch next iteration's {key, mask} while data is in flight
        const int nbase = base + stride;
        uint2 rm_next = rm;
        if (nbase < NNZ) rm_next = g_rcm[nbase + grp];

        float s = dot8h(aL, bL) + dot8h(aH, bH);

        s += __shfl_xor_sync(0xFFFFFFFFu, s, 4);
        s += __shfl_xor_sync(0xFFFFFFFFu, s, 2);
        s += __shfl_xor_sync(0xFFFFFFFFu, s, 1);

        if (sub == 0)
            out[base + grp] = __uint_as_float(rm.y) + s;

        base = nbase;
        rm   = rm_next;
    }
}

extern "C" void kernel_launch(void* const* d_in, const int* in_sizes, int n_in,
                              void* d_out, int out_size) {
    const float* mask_vals = (const float*)d_in[0];
    const int*   rows      = (const int*)d_in[1];
    const int*   cols      = (const int*)d_in[2];
    const float* mat1      = (const float*)d_in[3];
    const float* mat2      = (const float*)d_in[4];
    float*       out       = (float*)d_out;

    prep_k<<<T2_BLOCKS + C1_BLOCKS + RC_BLOCKS, 256>>>(mat1, mat2, rows, cols,
                                                       mask_vals);

    // Launch sddmm with programmatic stream serialization (PDL): it may
    // begin its prologue while prep drains; the grid-dependency sync inside
    // gates all accesses to prep's outputs. Falls back to serial semantics.
    cudaLaunchConfig_t cfg = {};
    cfg.gridDim  = dim3(148 * 8, 1, 1);
    cfg.blockDim = dim3(256, 1, 1);
    cudaLaunchAttribute attrs[1];
    attrs[0].id = cudaLaunchAttributeProgrammaticStreamSerialization;
    attrs[0].val.programmaticStreamSerializationAllowed = 1;
    cfg.attrs    = attrs;
    cfg.numAttrs = 1;
    cudaLaunchKernelEx(&cfg, sddmm_k, out);
}